// round 9
// baseline (speedup 1.0000x reference)
#include <cuda_runtime.h>
#include <math.h>

#define FDIM 128
#define HEADS 4
#define CH 32
#define NMAX 50000
#define EMAX 1600000
#define EPMAX (EMAX + NMAX)

// ---- static device scratch (allocation-free) ----
__device__ float g_h [NMAX * FDIM];
__device__ float g_xa[NMAX * FDIM];
__device__ float g_xb[NMAX * FDIM];
__device__ float g_as[NMAX * HEADS];
__device__ float g_ad[NMAX * HEADS];
__device__ int   g_cnt [NMAX];
__device__ int   g_rptr[NMAX];
__device__ int   g_fill[NMAX];
__device__ int   g_csrc[EPMAX];

// packed f32x2 helpers (FFMA2 — PTX-only, ptxas never auto-fuses)
__device__ __forceinline__ void ffma2(unsigned long long& d,
                                      unsigned long long a,
                                      unsigned long long b) {
    asm("fma.rn.f32x2 %0, %1, %2, %0;" : "+l"(d) : "l"(a), "l"(b));
}
__device__ __forceinline__ unsigned long long dup2(float x) {
    unsigned long long r;
    asm("mov.b64 %0, {%1, %1};" : "=l"(r) : "f"(x));
    return r;
}

// =============== CSR build (counting sort by dst) ===============
__global__ void hist_kernel(const int* __restrict__ ei, int* __restrict__ cnt,
                            int E, int EP) {
    int e = blockIdx.x * blockDim.x + threadIdx.x;
    if (e >= EP) return;
    int dst = (e < E) ? ei[E + e] : (e - E);
    atomicAdd(&cnt[dst], 1);
}

// single-block multi-pass exclusive scan over cnt[N] -> rptr/fill
__global__ void scan_all_kernel(const int* __restrict__ cnt,
                                int* __restrict__ rptr,
                                int* __restrict__ fill, int N) {
    __shared__ int sh[1024];
    int t = threadIdx.x;
    int running = 0;
    for (int base = 0; base < N; base += 4096) {
        int v[4]; int s = 0;
        #pragma unroll
        for (int j = 0; j < 4; j++) {
            int idx = base + t * 4 + j;
            v[j] = (idx < N) ? cnt[idx] : 0;
            s += v[j];
        }
        sh[t] = s;
        __syncthreads();
        #pragma unroll
        for (int off = 1; off < 1024; off <<= 1) {
            int x = (t >= off) ? sh[t - off] : 0;
            __syncthreads();
            sh[t] += x;
            __syncthreads();
        }
        int run = running + (t ? sh[t - 1] : 0);
        #pragma unroll
        for (int j = 0; j < 4; j++) {
            int idx = base + t * 4 + j;
            if (idx < N) { rptr[idx] = run; fill[idx] = run; }
            run += v[j];
        }
        running += sh[1023];
        __syncthreads();
    }
}

__global__ void scatter_kernel(const int* __restrict__ ei, int* __restrict__ fill,
                               int* __restrict__ csrc, int E, int EP) {
    int e = blockIdx.x * blockDim.x + threadIdx.x;
    if (e >= EP) return;
    int src, dst;
    if (e < E) { src = ei[e]; dst = ei[E + e]; }
    else       { src = dst = e - E; }
    int pos = atomicAdd(&fill[dst], 1);
    csrc[pos] = src;
}

// =============== GEMM (FFMA2 mainloop) + fused alpha epilogue ===============
#define GEMM_SMEM_BYTES ((128 * 132 + 128 * 128) * 4)
__global__ void __launch_bounds__(256, 1)
gemm_kernel(const float* __restrict__ A,
            const float* __restrict__ B,
            const float* __restrict__ att_s,
            const float* __restrict__ att_d,
            float* __restrict__ C,
            float* __restrict__ as_,
            float* __restrict__ ad_,
            int N) {
    extern __shared__ float smem[];
    float (*As)[132] = (float(*)[132])smem;               // [k][row]
    float (*Bs)[128] = (float(*)[128])(smem + 128 * 132); // [k][col]
    int tid = threadIdx.x;
    int tx = tid & 15;
    int ty = tid >> 4;
    int rowBlock = blockIdx.x * 128;

    #pragma unroll
    for (int i = 0; i < 16; i++) {
        int idx = i * 256 + tid;
        int row = idx >> 5;
        int c4  = idx & 31;
        int gr = rowBlock + row;
        float4 av = make_float4(0.f, 0.f, 0.f, 0.f);
        if (gr < N) av = *(const float4*)&A[(size_t)gr * FDIM + c4 * 4];
        As[c4 * 4 + 0][row] = av.x;
        As[c4 * 4 + 1][row] = av.y;
        As[c4 * 4 + 2][row] = av.z;
        As[c4 * 4 + 3][row] = av.w;
        *(float4*)&Bs[row][c4 * 4] = *(const float4*)&B[(size_t)row * FDIM + c4 * 4];
    }
    __syncthreads();

    unsigned long long acc2[4][8];
    #pragma unroll
    for (int ip = 0; ip < 4; ip++)
        #pragma unroll
        for (int j = 0; j < 8; j++) acc2[ip][j] = 0ull;

    #pragma unroll 4
    for (int kk = 0; kk < 128; kk++) {
        unsigned long long a2[4];
        float bf[8];
        *(float4*)&a2[0] = *(float4*)&As[kk][ty * 8];
        *(float4*)&a2[2] = *(float4*)&As[kk][ty * 8 + 4];
        *(float4*)&bf[0] = *(float4*)&Bs[kk][tx * 8];
        *(float4*)&bf[4] = *(float4*)&Bs[kk][tx * 8 + 4];
        #pragma unroll
        for (int j = 0; j < 8; j++) {
            unsigned long long bd = dup2(bf[j]);
            #pragma unroll
            for (int ip = 0; ip < 4; ip++)
                ffma2(acc2[ip][j], a2[ip], bd);
        }
    }

    float sa[8], da[8];
    #pragma unroll
    for (int j = 0; j < 8; j++) {
        sa[j] = att_s[tx * 8 + j];
        da[j] = att_d[tx * 8 + j];
    }
    int head = tx >> 2;
    #pragma unroll
    for (int i = 0; i < 8; i++) {
        int ip = i >> 1;
        float r[8];
        #pragma unroll
        for (int j = 0; j < 8; j++) {
            float2 p = *(float2*)&acc2[ip][j];
            r[j] = (i & 1) ? p.y : p.x;
        }
        int gr = rowBlock + ty * 8 + i;
        if (gr < N) {
            *(float4*)&C[(size_t)gr * FDIM + tx * 8]     = *(float4*)&r[0];
            *(float4*)&C[(size_t)gr * FDIM + tx * 8 + 4] = *(float4*)&r[4];
        }
        float ps = 0.f, pd = 0.f;
        #pragma unroll
        for (int j = 0; j < 8; j++) {
            ps += r[j] * sa[j];
            pd += r[j] * da[j];
        }
        ps += __shfl_down_sync(0xffffffffu, ps, 2);
        pd += __shfl_down_sync(0xffffffffu, pd, 2);
        ps += __shfl_down_sync(0xffffffffu, ps, 1);
        pd += __shfl_down_sync(0xffffffffu, pd, 1);
        if ((tx & 3) == 0 && gr < N) {
            as_[gr * HEADS + head] = ps;
            ad_[gr * HEADS + head] = pd;
        }
    }
}

// =============== fused softmax + aggregation: warp per dst, 8-edge batches ===============
__global__ void aggr_kernel(const int* __restrict__ csrc,
                            const int* __restrict__ rptr,
                            const int* __restrict__ cnt,
                            const float* __restrict__ as_,
                            const float* __restrict__ ad_,
                            const float* __restrict__ h,
                            const float* __restrict__ bias,
                            float* __restrict__ out, int N) {
    int gtid = blockIdx.x * blockDim.x + threadIdx.x;
    int dst = gtid >> 5;
    int lane = gtid & 31;
    if (dst >= N) return;
    int beg = rptr[dst];
    int deg = cnt[dst];
    int hd = lane >> 3;
    float adv = ad_[dst * HEADS + hd];
    float acc0 = 0.f, acc1 = 0.f, acc2 = 0.f, acc3 = 0.f;
    float ssum = 0.f;

    for (int i0 = 0; i0 < deg; i0 += 32) {
        int li = i0 + lane;
        int mySrc = csrc[beg + ((li < deg) ? li : (deg - 1))];
        int m = min(32, deg - i0);
        int j = 0;
        for (; j + 8 <= m; j += 8) {
            int s[8]; float asv[8]; float4 hv[8];
            #pragma unroll
            for (int q = 0; q < 8; q++)
                s[q] = __shfl_sync(0xffffffffu, mySrc, j + q);
            #pragma unroll
            for (int q = 0; q < 8; q++)
                asv[q] = as_[s[q] * HEADS + hd];
            #pragma unroll
            for (int q = 0; q < 8; q++)
                hv[q] = *(const float4*)&h[(size_t)s[q] * FDIM + lane * 4];
            #pragma unroll
            for (int q = 0; q < 8; q++) {
                float e = asv[q] + adv;
                e = (e > 0.f) ? e : 0.2f * e;
                float ex = __expf(e);
                ssum += ex;
                acc0 += hv[q].x * ex;
                acc1 += hv[q].y * ex;
                acc2 += hv[q].z * ex;
                acc3 += hv[q].w * ex;
            }
        }
        for (; j < m; j++) {
            int src = __shfl_sync(0xffffffffu, mySrc, j);
            float e = as_[src * HEADS + hd] + adv;
            e = (e > 0.f) ? e : 0.2f * e;
            float ex = __expf(e);
            ssum += ex;
            float4 hv = *(const float4*)&h[(size_t)src * FDIM + lane * 4];
            acc0 += hv.x * ex;
            acc1 += hv.y * ex;
            acc2 += hv.z * ex;
            acc3 += hv.w * ex;
        }
    }
    float inv = 1.f / (ssum + 1e-16f);
    float4 b4 = *(const float4*)&bias[lane * 4];
    float4 o = make_float4(acc0 * inv + b4.x, acc1 * inv + b4.y,
                           acc2 * inv + b4.z, acc3 * inv + b4.w);
    *(float4*)&out[(size_t)dst * FDIM + lane * 4] = o;
}

// =============== MLP head ===============
__global__ void mlp_kernel(const float* __restrict__ x3,
                           const float* __restrict__ x0,
                           const float* __restrict__ W1,
                           const float* __restrict__ b1,
                           const float* __restrict__ W2,
                           const float* __restrict__ b2,
                           float* __restrict__ out, int N) {
    __shared__ float W1s[256 * 32];
    __shared__ float W2s[32];
    __shared__ float b1s[32];
    int tid = threadIdx.x;
    for (int i = tid; i < 256 * 32; i += blockDim.x) W1s[i] = W1[i];
    if (tid < 32) { W2s[tid] = W2[tid]; b1s[tid] = b1[tid]; }
    __syncthreads();
    int warp = tid >> 5, lane = tid & 31;
    int node = blockIdx.x * (blockDim.x >> 5) + warp;
    if (node >= N) return;
    float acc = 0.f;
    #pragma unroll
    for (int blk = 0; blk < 8; blk++) {
        const float* xp = (blk < 4) ? &x3[(size_t)node * FDIM + blk * 32]
                                    : &x0[(size_t)node * FDIM + (blk - 4) * 32];
        float xv = xp[lane];
        #pragma unroll
        for (int i = 0; i < 32; i++) {
            float v = __shfl_sync(0xffffffffu, xv, i);
            acc += v * W1s[(blk * 32 + i) * 32 + lane];
        }
    }
    float hv = fmaxf(acc + b1s[lane], 0.f);
    float p = hv * W2s[lane];
    #pragma unroll
    for (int off = 16; off; off >>= 1)
        p += __shfl_down_sync(0xffffffffu, p, off);
    if (lane == 0)
        out[node] = 1.f / (1.f + __expf(-(p + b2[0])));
}

// =============== host launcher ===============
extern "C" void kernel_launch(void* const* d_in, const int* in_sizes, int n_in,
                              void* d_out, int out_size) {
    const float* x       = (const float*)d_in[0];
    const int*   ei      = (const int*)  d_in[1];
    const float* W       = (const float*)d_in[2];
    const float* att_src = (const float*)d_in[3];
    const float* att_dst = (const float*)d_in[4];
    const float* b_conv  = (const float*)d_in[5];
    const float* W1      = (const float*)d_in[6];
    const float* b1      = (const float*)d_in[7];
    const float* W2      = (const float*)d_in[8];
    const float* b2      = (const float*)d_in[9];

    int N  = in_sizes[0] / FDIM;
    int E  = in_sizes[1] / 2;
    int L  = in_sizes[2] / (FDIM * FDIM);
    int EP = E + N;

    float *hb, *xa, *xb, *asb, *adb;
    int *cnt, *rptr, *fill, *csrc;
    cudaGetSymbolAddress((void**)&hb,   g_h);
    cudaGetSymbolAddress((void**)&xa,   g_xa);
    cudaGetSymbolAddress((void**)&xb,   g_xb);
    cudaGetSymbolAddress((void**)&asb,  g_as);
    cudaGetSymbolAddress((void**)&adb,  g_ad);
    cudaGetSymbolAddress((void**)&cnt,  g_cnt);
    cudaGetSymbolAddress((void**)&rptr, g_rptr);
    cudaGetSymbolAddress((void**)&fill, g_fill);
    cudaGetSymbolAddress((void**)&csrc, g_csrc);

    static bool init_done = false;
    static cudaStream_t s2;
    static cudaEvent_t ev0, ev1;
    if (!init_done) {
        cudaFuncSetAttribute(gemm_kernel,
                             cudaFuncAttributeMaxDynamicSharedMemorySize,
                             GEMM_SMEM_BYTES);
        cudaStreamCreateWithFlags(&s2, cudaStreamNonBlocking);
        cudaEventCreateWithFlags(&ev0, cudaEventDisableTiming);
        cudaEventCreateWithFlags(&ev1, cudaEventDisableTiming);
        init_done = true;
    }

    // ---- fork: CSR build on s2, concurrent with gemm0 on main stream ----
    cudaEventRecord(ev0, 0);
    cudaStreamWaitEvent(s2, ev0, 0);
    cudaMemsetAsync(cnt, 0, (size_t)N * sizeof(int), s2);
    hist_kernel<<<(EP + 255) / 256, 256, 0, s2>>>(ei, cnt, E, EP);
    scan_all_kernel<<<1, 1024, 0, s2>>>(cnt, rptr, fill, N);
    scatter_kernel<<<(EP + 255) / 256, 256, 0, s2>>>(ei, fill, csrc, E, EP);
    cudaEventRecord(ev1, s2);

    int gemm_grid = (N + 127) / 128;
    int aggr_grid = (int)(((size_t)N * 32 + 255) / 256);
    float* bufs[2] = {xa, xb};

    // layer 0 GEMM overlaps the CSR build
    gemm_kernel<<<gemm_grid, 256, GEMM_SMEM_BYTES>>>(
        x, W, att_src, att_dst, hb, asb, adb, N);
    cudaStreamWaitEvent(0, ev1, 0);   // join: aggr needs CSR

    const float* xin;
    for (int l = 0; l < L; l++) {
        float* outb = bufs[l & 1];
        if (l > 0) {
            gemm_kernel<<<gemm_grid, 256, GEMM_SMEM_BYTES>>>(
                bufs[(l - 1) & 1], W + (size_t)l * FDIM * FDIM,
                att_src + l * HEADS * CH, att_dst + l * HEADS * CH,
                hb, asb, adb, N);
        }
        aggr_kernel<<<aggr_grid, 256>>>(csrc, rptr, cnt, asb, adb, hb,
                                        b_conv + l * FDIM, outb, N);
        xin = outb;
    }
    mlp_kernel<<<(N + 7) / 8, 256>>>(xin, x, W1, b1, W2, b2, (float*)d_out, N);
}

// round 10
// speedup vs baseline: 1.0878x; 1.0878x over previous
#include <cuda_runtime.h>
#include <math.h>

#define FDIM 128
#define HEADS 4
#define CH 32
#define NMAX 50000
#define EMAX 1600000
#define EPMAX (EMAX + NMAX)

// ---- static device scratch (allocation-free) ----
__device__ float g_h [NMAX * FDIM];
__device__ float g_xa[NMAX * FDIM];
__device__ float g_xb[NMAX * FDIM];
__device__ float g_as[NMAX * HEADS];
__device__ float g_ad[NMAX * HEADS];
__device__ int   g_cnt [NMAX];
__device__ int   g_rptr[NMAX];
__device__ int   g_fill[NMAX];
__device__ int   g_bsum[64];
__device__ int   g_boff[64];
__device__ int   g_csrc[EPMAX];

// packed f32x2 helpers (FFMA2 — PTX-only, ptxas never auto-fuses)
__device__ __forceinline__ void ffma2(unsigned long long& d,
                                      unsigned long long a,
                                      unsigned long long b) {
    asm("fma.rn.f32x2 %0, %1, %2, %0;" : "+l"(d) : "l"(a), "l"(b));
}
__device__ __forceinline__ unsigned long long dup2(float x) {
    unsigned long long r;
    asm("mov.b64 %0, {%1, %1};" : "=l"(r) : "f"(x));
    return r;
}

// =============== CSR build (counting sort by dst) ===============
__global__ void hist_kernel(const int* __restrict__ ei, int* __restrict__ cnt,
                            int E, int EP) {
    int e = blockIdx.x * blockDim.x + threadIdx.x;
    if (e >= EP) return;
    int dst = (e < E) ? ei[E + e] : (e - E);
    atomicAdd(&cnt[dst], 1);
}

__global__ void scan1_kernel(const int* __restrict__ cnt, int* __restrict__ rptr,
                             int* __restrict__ bsum, int N) {
    __shared__ int sh[256];
    int t = threadIdx.x;
    int base = blockIdx.x * 1024;
    int v[4]; int s = 0;
    #pragma unroll
    for (int j = 0; j < 4; j++) {
        int idx = base + t * 4 + j;
        v[j] = (idx < N) ? cnt[idx] : 0;
        s += v[j];
    }
    sh[t] = s; __syncthreads();
    #pragma unroll
    for (int off = 1; off < 256; off <<= 1) {
        int x = (t >= off) ? sh[t - off] : 0;
        __syncthreads();
        sh[t] += x;
        __syncthreads();
    }
    int run = (t ? sh[t - 1] : 0);
    #pragma unroll
    for (int j = 0; j < 4; j++) {
        int idx = base + t * 4 + j;
        if (idx < N) rptr[idx] = run;
        run += v[j];
    }
    if (t == 255) bsum[blockIdx.x] = sh[255];
}

__global__ void scan_bsum_kernel(const int* __restrict__ bsum,
                                 int* __restrict__ boff, int nb) {
    __shared__ int sh[64];
    int t = threadIdx.x;
    sh[t] = (t < nb) ? bsum[t] : 0;
    __syncthreads();
    #pragma unroll
    for (int off = 1; off < 64; off <<= 1) {
        int x = (t >= off) ? sh[t - off] : 0;
        __syncthreads();
        sh[t] += x;
        __syncthreads();
    }
    if (t < nb) boff[t] = (t ? sh[t - 1] : 0);
}

__global__ void scan2_kernel(int* __restrict__ rptr, int* __restrict__ fill,
                             const int* __restrict__ boff, int N) {
    int off = boff[blockIdx.x];
    int base = blockIdx.x * 1024;
    #pragma unroll
    for (int j = 0; j < 4; j++) {
        int idx = base + threadIdx.x * 4 + j;
        if (idx < N) {
            int r = rptr[idx] + off;
            rptr[idx] = r;
            fill[idx] = r;
        }
    }
}

__global__ void scatter_kernel(const int* __restrict__ ei, int* __restrict__ fill,
                               int* __restrict__ csrc, int E, int EP) {
    int e = blockIdx.x * blockDim.x + threadIdx.x;
    if (e >= EP) return;
    int src, dst;
    if (e < E) { src = ei[e]; dst = ei[E + e]; }
    else       { src = dst = e - E; }
    int pos = atomicAdd(&fill[dst], 1);
    csrc[pos] = src;
}

// =============== GEMM: 64x128 block tile, BK=32 double-buffered, FFMA2 ===============
// 128 threads, 8x8 microtile, alpha epilogue fused. 3 CTAs/SM target.
#define GEMM_BM 64
#define GEMM_BK 32
#define AS_STRIDE 68
#define GEMM_STAGE_FLOATS (GEMM_BK * AS_STRIDE + GEMM_BK * 128)   // 2176+4096
#define GEMM_SMEM_BYTES (2 * GEMM_STAGE_FLOATS * 4)               // 50176 B

__global__ void __launch_bounds__(128)
gemm_kernel(const float* __restrict__ A,
            const float* __restrict__ B,
            const float* __restrict__ att_s,
            const float* __restrict__ att_d,
            float* __restrict__ C,
            float* __restrict__ as_,
            float* __restrict__ ad_,
            int N) {
    extern __shared__ float smem[];
    int tid = threadIdx.x;
    int tx = tid & 15;                 // cols tx*8 .. tx*8+7
    int ty = tid >> 4;                 // rows ty*8 .. ty*8+7 (0..7)
    int rowBlock = blockIdx.x * GEMM_BM;

    float4 rA[4], rB[8];

    // prologue: chunk 0 gmem -> regs -> smem buf 0
    {
        int k0 = 0;
        #pragma unroll
        for (int q = 0; q < 4; q++) {
            int idx = q * 128 + tid;
            int row = idx >> 3, c4 = idx & 7;
            int gr = rowBlock + row;
            rA[q] = (gr < N) ? *(const float4*)&A[(size_t)gr * FDIM + k0 + c4 * 4]
                             : make_float4(0.f, 0.f, 0.f, 0.f);
        }
        #pragma unroll
        for (int q = 0; q < 8; q++) {
            int idx = q * 128 + tid;
            int row = idx >> 5, c4 = idx & 31;
            rB[q] = *(const float4*)&B[(size_t)(k0 + row) * FDIM + c4 * 4];
        }
        float* As = smem;
        float* Bs = smem + GEMM_BK * AS_STRIDE;
        #pragma unroll
        for (int q = 0; q < 4; q++) {
            int idx = q * 128 + tid;
            int row = idx >> 3, c4 = idx & 7;
            As[(c4 * 4 + 0) * AS_STRIDE + row] = rA[q].x;
            As[(c4 * 4 + 1) * AS_STRIDE + row] = rA[q].y;
            As[(c4 * 4 + 2) * AS_STRIDE + row] = rA[q].z;
            As[(c4 * 4 + 3) * AS_STRIDE + row] = rA[q].w;
        }
        #pragma unroll
        for (int q = 0; q < 8; q++) {
            int idx = q * 128 + tid;
            int row = idx >> 5, c4 = idx & 31;
            *(float4*)&Bs[row * 128 + c4 * 4] = rB[q];
        }
    }
    __syncthreads();

    unsigned long long acc2[4][8];
    #pragma unroll
    for (int ip = 0; ip < 4; ip++)
        #pragma unroll
        for (int j = 0; j < 8; j++) acc2[ip][j] = 0ull;

    #pragma unroll
    for (int c = 0; c < 4; c++) {
        // prefetch next chunk into regs (overlaps compute below)
        if (c < 3) {
            int k0 = (c + 1) * GEMM_BK;
            #pragma unroll
            for (int q = 0; q < 4; q++) {
                int idx = q * 128 + tid;
                int row = idx >> 3, c4 = idx & 7;
                int gr = rowBlock + row;
                rA[q] = (gr < N) ? *(const float4*)&A[(size_t)gr * FDIM + k0 + c4 * 4]
                                 : make_float4(0.f, 0.f, 0.f, 0.f);
            }
            #pragma unroll
            for (int q = 0; q < 8; q++) {
                int idx = q * 128 + tid;
                int row = idx >> 5, c4 = idx & 31;
                rB[q] = *(const float4*)&B[(size_t)(k0 + row) * FDIM + c4 * 4];
            }
        }

        const float* As = smem + (c & 1) * GEMM_STAGE_FLOATS;
        const float* Bs = As + GEMM_BK * AS_STRIDE;
        #pragma unroll 8
        for (int kk = 0; kk < GEMM_BK; kk++) {
            unsigned long long a2[4];
            float bf[8];
            *(float4*)&a2[0] = *(const float4*)&As[kk * AS_STRIDE + ty * 8];
            *(float4*)&a2[2] = *(const float4*)&As[kk * AS_STRIDE + ty * 8 + 4];
            *(float4*)&bf[0] = *(const float4*)&Bs[kk * 128 + tx * 8];
            *(float4*)&bf[4] = *(const float4*)&Bs[kk * 128 + tx * 8 + 4];
            #pragma unroll
            for (int j = 0; j < 8; j++) {
                unsigned long long bd = dup2(bf[j]);
                #pragma unroll
                for (int ip = 0; ip < 4; ip++)
                    ffma2(acc2[ip][j], a2[ip], bd);
            }
        }

        if (c < 3) {
            float* Asw = smem + ((c + 1) & 1) * GEMM_STAGE_FLOATS;
            float* Bsw = Asw + GEMM_BK * AS_STRIDE;
            #pragma unroll
            for (int q = 0; q < 4; q++) {
                int idx = q * 128 + tid;
                int row = idx >> 3, c4 = idx & 7;
                Asw[(c4 * 4 + 0) * AS_STRIDE + row] = rA[q].x;
                Asw[(c4 * 4 + 1) * AS_STRIDE + row] = rA[q].y;
                Asw[(c4 * 4 + 2) * AS_STRIDE + row] = rA[q].z;
                Asw[(c4 * 4 + 3) * AS_STRIDE + row] = rA[q].w;
            }
            #pragma unroll
            for (int q = 0; q < 8; q++) {
                int idx = q * 128 + tid;
                int row = idx >> 5, c4 = idx & 31;
                *(float4*)&Bsw[row * 128 + c4 * 4] = rB[q];
            }
        }
        __syncthreads();
    }

    // ---- epilogue: store h + fused alpha ----
    float sa[8], da[8];
    #pragma unroll
    for (int j = 0; j < 8; j++) {
        sa[j] = att_s[tx * 8 + j];
        da[j] = att_d[tx * 8 + j];
    }
    int head = tx >> 2;
    #pragma unroll
    for (int i = 0; i < 8; i++) {
        int ip = i >> 1;
        float r[8];
        #pragma unroll
        for (int j = 0; j < 8; j++) {
            float2 p = *(float2*)&acc2[ip][j];
            r[j] = (i & 1) ? p.y : p.x;
        }
        int gr = rowBlock + ty * 8 + i;
        if (gr < N) {
            *(float4*)&C[(size_t)gr * FDIM + tx * 8]     = *(float4*)&r[0];
            *(float4*)&C[(size_t)gr * FDIM + tx * 8 + 4] = *(float4*)&r[4];
        }
        float ps = 0.f, pd = 0.f;
        #pragma unroll
        for (int j = 0; j < 8; j++) {
            ps += r[j] * sa[j];
            pd += r[j] * da[j];
        }
        ps += __shfl_down_sync(0xffffffffu, ps, 2);
        pd += __shfl_down_sync(0xffffffffu, pd, 2);
        ps += __shfl_down_sync(0xffffffffu, ps, 1);
        pd += __shfl_down_sync(0xffffffffu, pd, 1);
        if ((tx & 3) == 0 && gr < N) {
            as_[gr * HEADS + head] = ps;
            ad_[gr * HEADS + head] = pd;
        }
    }
}

// =============== fused softmax + aggregation: warp per dst, 8-edge batches ===============
__global__ void aggr_kernel(const int* __restrict__ csrc,
                            const int* __restrict__ rptr,
                            const int* __restrict__ cnt,
                            const float* __restrict__ as_,
                            const float* __restrict__ ad_,
                            const float* __restrict__ h,
                            const float* __restrict__ bias,
                            float* __restrict__ out, int N) {
    int gtid = blockIdx.x * blockDim.x + threadIdx.x;
    int dst = gtid >> 5;
    int lane = gtid & 31;
    if (dst >= N) return;
    int beg = rptr[dst];
    int deg = cnt[dst];
    int hd = lane >> 3;
    float adv = ad_[dst * HEADS + hd];
    float acc0 = 0.f, acc1 = 0.f, acc2 = 0.f, acc3 = 0.f;
    float ssum = 0.f;

    for (int i0 = 0; i0 < deg; i0 += 32) {
        int li = i0 + lane;
        int mySrc = csrc[beg + ((li < deg) ? li : (deg - 1))];
        int m = min(32, deg - i0);
        int j = 0;
        for (; j + 8 <= m; j += 8) {
            int s[8]; float asv[8]; float4 hv[8];
            #pragma unroll
            for (int q = 0; q < 8; q++)
                s[q] = __shfl_sync(0xffffffffu, mySrc, j + q);
            #pragma unroll
            for (int q = 0; q < 8; q++)
                asv[q] = as_[s[q] * HEADS + hd];
            #pragma unroll
            for (int q = 0; q < 8; q++)
                hv[q] = *(const float4*)&h[(size_t)s[q] * FDIM + lane * 4];
            #pragma unroll
            for (int q = 0; q < 8; q++) {
                float e = asv[q] + adv;
                e = (e > 0.f) ? e : 0.2f * e;
                float ex = __expf(e);
                ssum += ex;
                acc0 += hv[q].x * ex;
                acc1 += hv[q].y * ex;
                acc2 += hv[q].z * ex;
                acc3 += hv[q].w * ex;
            }
        }
        for (; j < m; j++) {
            int src = __shfl_sync(0xffffffffu, mySrc, j);
            float e = as_[src * HEADS + hd] + adv;
            e = (e > 0.f) ? e : 0.2f * e;
            float ex = __expf(e);
            ssum += ex;
            float4 hv = *(const float4*)&h[(size_t)src * FDIM + lane * 4];
            acc0 += hv.x * ex;
            acc1 += hv.y * ex;
            acc2 += hv.z * ex;
            acc3 += hv.w * ex;
        }
    }
    float inv = 1.f / (ssum + 1e-16f);
    float4 b4 = *(const float4*)&bias[lane * 4];
    float4 o = make_float4(acc0 * inv + b4.x, acc1 * inv + b4.y,
                           acc2 * inv + b4.z, acc3 * inv + b4.w);
    *(float4*)&out[(size_t)dst * FDIM + lane * 4] = o;
}

// =============== MLP head ===============
__global__ void mlp_kernel(const float* __restrict__ x3,
                           const float* __restrict__ x0,
                           const float* __restrict__ W1,
                           const float* __restrict__ b1,
                           const float* __restrict__ W2,
                           const float* __restrict__ b2,
                           float* __restrict__ out, int N) {
    __shared__ float W1s[256 * 32];
    __shared__ float W2s[32];
    __shared__ float b1s[32];
    int tid = threadIdx.x;
    for (int i = tid; i < 256 * 32; i += blockDim.x) W1s[i] = W1[i];
    if (tid < 32) { W2s[tid] = W2[tid]; b1s[tid] = b1[tid]; }
    __syncthreads();
    int warp = tid >> 5, lane = tid & 31;
    int node = blockIdx.x * (blockDim.x >> 5) + warp;
    if (node >= N) return;
    float acc = 0.f;
    #pragma unroll
    for (int blk = 0; blk < 8; blk++) {
        const float* xp = (blk < 4) ? &x3[(size_t)node * FDIM + blk * 32]
                                    : &x0[(size_t)node * FDIM + (blk - 4) * 32];
        float xv = xp[lane];
        #pragma unroll
        for (int i = 0; i < 32; i++) {
            float v = __shfl_sync(0xffffffffu, xv, i);
            acc += v * W1s[(blk * 32 + i) * 32 + lane];
        }
    }
    float hv = fmaxf(acc + b1s[lane], 0.f);
    float p = hv * W2s[lane];
    #pragma unroll
    for (int off = 16; off; off >>= 1)
        p += __shfl_down_sync(0xffffffffu, p, off);
    if (lane == 0)
        out[node] = 1.f / (1.f + __expf(-(p + b2[0])));
}

// =============== host launcher ===============
extern "C" void kernel_launch(void* const* d_in, const int* in_sizes, int n_in,
                              void* d_out, int out_size) {
    const float* x       = (const float*)d_in[0];
    const int*   ei      = (const int*)  d_in[1];
    const float* W       = (const float*)d_in[2];
    const float* att_src = (const float*)d_in[3];
    const float* att_dst = (const float*)d_in[4];
    const float* b_conv  = (const float*)d_in[5];
    const float* W1      = (const float*)d_in[6];
    const float* b1      = (const float*)d_in[7];
    const float* W2      = (const float*)d_in[8];
    const float* b2      = (const float*)d_in[9];

    int N  = in_sizes[0] / FDIM;
    int E  = in_sizes[1] / 2;
    int L  = in_sizes[2] / (FDIM * FDIM);
    int EP = E + N;

    float *hb, *xa, *xb, *asb, *adb;
    int *cnt, *rptr, *fill, *bsum, *boff, *csrc;
    cudaGetSymbolAddress((void**)&hb,   g_h);
    cudaGetSymbolAddress((void**)&xa,   g_xa);
    cudaGetSymbolAddress((void**)&xb,   g_xb);
    cudaGetSymbolAddress((void**)&asb,  g_as);
    cudaGetSymbolAddress((void**)&adb,  g_ad);
    cudaGetSymbolAddress((void**)&cnt,  g_cnt);
    cudaGetSymbolAddress((void**)&rptr, g_rptr);
    cudaGetSymbolAddress((void**)&fill, g_fill);
    cudaGetSymbolAddress((void**)&bsum, g_bsum);
    cudaGetSymbolAddress((void**)&boff, g_boff);
    cudaGetSymbolAddress((void**)&csrc, g_csrc);

    static bool init_done = false;
    if (!init_done) {
        cudaFuncSetAttribute(gemm_kernel,
                             cudaFuncAttributeMaxDynamicSharedMemorySize,
                             GEMM_SMEM_BYTES);
        init_done = true;
    }

    // ---- CSR build (serial; overlap attempt in R9 regressed) ----
    int nb_scan = (N + 1023) / 1024;
    cudaMemsetAsync(cnt, 0, (size_t)N * sizeof(int), 0);
    hist_kernel<<<(EP + 255) / 256, 256>>>(ei, cnt, E, EP);
    scan1_kernel<<<nb_scan, 256>>>(cnt, rptr, bsum, N);
    scan_bsum_kernel<<<1, 64>>>(bsum, boff, nb_scan);
    scan2_kernel<<<nb_scan, 256>>>(rptr, fill, boff, N);
    scatter_kernel<<<(EP + 255) / 256, 256>>>(ei, fill, csrc, E, EP);

    // ---- layers ----
    const float* xin = x;
    float* bufs[2] = {xa, xb};
    int gemm_grid = (N + GEMM_BM - 1) / GEMM_BM;
    int aggr_grid = (int)(((size_t)N * 32 + 255) / 256);

    for (int l = 0; l < L; l++) {
        float* outb = bufs[l & 1];
        gemm_kernel<<<gemm_grid, 128, GEMM_SMEM_BYTES>>>(
            xin, W + (size_t)l * FDIM * FDIM,
            att_src + l * HEADS * CH, att_dst + l * HEADS * CH,
            hb, asb, adb, N);
        aggr_kernel<<<aggr_grid, 256>>>(csrc, rptr, cnt, asb, adb, hb,
                                        b_conv + l * FDIM, outb, N);
        xin = outb;
    }
    mlp_kernel<<<(N + 7) / 8, 256>>>(xin, x, W1, b1, W2, b2, (float*)d_out, N);
}

// round 12
// speedup vs baseline: 1.1269x; 1.0359x over previous
#include <cuda_runtime.h>
#include <math.h>

#define FDIM 128
#define HEADS 4
#define CH 32
#define NMAX 50000
#define EMAX 1600000
#define EPMAX (EMAX + NMAX)

// ---- static device scratch (allocation-free) ----
__device__ float g_h [NMAX * FDIM];
__device__ float g_xa[NMAX * FDIM];
__device__ float g_xb[NMAX * FDIM];
__device__ float g_as[NMAX * HEADS];
__device__ float g_ad[NMAX * HEADS];
__device__ int   g_cnt [NMAX];
__device__ int   g_rptr[NMAX];
__device__ int   g_fill[NMAX];
__device__ int   g_bsum[64];
__device__ int   g_csrc[EPMAX];

// packed f32x2 helpers (FFMA2 — PTX-only, ptxas never auto-fuses)
__device__ __forceinline__ void ffma2(unsigned long long& d,
                                      unsigned long long a,
                                      unsigned long long b) {
    asm("fma.rn.f32x2 %0, %1, %2, %0;" : "+l"(d) : "l"(a), "l"(b));
}
__device__ __forceinline__ unsigned long long dup2(float x) {
    unsigned long long r;
    asm("mov.b64 %0, {%1, %1};" : "=l"(r) : "f"(x));
    return r;
}

// =============== CSR build (counting sort by dst) ===============
__global__ void hist_kernel(const int* __restrict__ ei, int* __restrict__ cnt,
                            int E, int EP) {
    int e = blockIdx.x * blockDim.x + threadIdx.x;
    if (e >= EP) return;
    int dst = (e < E) ? ei[E + e] : (e - E);
    atomicAdd(&cnt[dst], 1);
}

__global__ void scan1_kernel(const int* __restrict__ cnt, int* __restrict__ rptr,
                             int* __restrict__ bsum, int N) {
    __shared__ int sh[256];
    int t = threadIdx.x;
    int base = blockIdx.x * 1024;
    int v[4]; int s = 0;
    #pragma unroll
    for (int j = 0; j < 4; j++) {
        int idx = base + t * 4 + j;
        v[j] = (idx < N) ? cnt[idx] : 0;
        s += v[j];
    }
    sh[t] = s; __syncthreads();
    #pragma unroll
    for (int off = 1; off < 256; off <<= 1) {
        int x = (t >= off) ? sh[t - off] : 0;
        __syncthreads();
        sh[t] += x;
        __syncthreads();
    }
    int run = (t ? sh[t - 1] : 0);
    #pragma unroll
    for (int j = 0; j < 4; j++) {
        int idx = base + t * 4 + j;
        if (idx < N) rptr[idx] = run;
        run += v[j];
    }
    if (t == 255) bsum[blockIdx.x] = sh[255];
}

// scan2: per-block offset = sum(bsum[0..blockIdx.x)) via masked warp reduction
__global__ void scan2_kernel(int* __restrict__ rptr, int* __restrict__ fill,
                             const int* __restrict__ bsum, int N, int nb) {
    __shared__ int offsh;
    int t = threadIdx.x;
    if (t < 32) {
        int bid = (int)blockIdx.x;
        int v = 0;
        if (t < nb && t < bid) v = bsum[t];
        int t2 = t + 32;
        if (t2 < nb && t2 < bid) v += bsum[t2];
        #pragma unroll
        for (int off = 16; off; off >>= 1)
            v += __shfl_down_sync(0xffffffffu, v, off);
        if (t == 0) offsh = v;
    }
    __syncthreads();
    int off = offsh;
    int base = blockIdx.x * 1024;
    #pragma unroll
    for (int j = 0; j < 4; j++) {
        int idx = base + t * 4 + j;
        if (idx < N) {
            int r = rptr[idx] + off;
            rptr[idx] = r;
            fill[idx] = r;
        }
    }
}

__global__ void scatter_kernel(const int* __restrict__ ei, int* __restrict__ fill,
                               int* __restrict__ csrc, int E, int EP) {
    int e = blockIdx.x * blockDim.x + threadIdx.x;
    if (e >= EP) return;
    int src, dst;
    if (e < E) { src = ei[e]; dst = ei[E + e]; }
    else       { src = dst = e - E; }
    int pos = atomicAdd(&fill[dst], 1);
    csrc[pos] = src;
}

// =============== GEMM: 64x128 block tile, BK=32 double-buffered, FFMA2 ===============
#define GEMM_BM 64
#define GEMM_BK 32
#define AS_STRIDE 68
#define GEMM_STAGE_FLOATS (GEMM_BK * AS_STRIDE + GEMM_BK * 128)
#define GEMM_SMEM_BYTES (2 * GEMM_STAGE_FLOATS * 4)

__global__ void __launch_bounds__(128)
gemm_kernel(const float* __restrict__ A,
            const float* __restrict__ B,
            const float* __restrict__ att_s,
            const float* __restrict__ att_d,
            float* __restrict__ C,
            float* __restrict__ as_,
            float* __restrict__ ad_,
            int N) {
    extern __shared__ float smem[];
    int tid = threadIdx.x;
    int tx = tid & 15;
    int ty = tid >> 4;
    int rowBlock = blockIdx.x * GEMM_BM;

    float4 rA[4], rB[8];

    {
        int k0 = 0;
        #pragma unroll
        for (int q = 0; q < 4; q++) {
            int idx = q * 128 + tid;
            int row = idx >> 3, c4 = idx & 7;
            int gr = rowBlock + row;
            rA[q] = (gr < N) ? *(const float4*)&A[(size_t)gr * FDIM + k0 + c4 * 4]
                             : make_float4(0.f, 0.f, 0.f, 0.f);
        }
        #pragma unroll
        for (int q = 0; q < 8; q++) {
            int idx = q * 128 + tid;
            int row = idx >> 5, c4 = idx & 31;
            rB[q] = *(const float4*)&B[(size_t)(k0 + row) * FDIM + c4 * 4];
        }
        float* As = smem;
        float* Bs = smem + GEMM_BK * AS_STRIDE;
        #pragma unroll
        for (int q = 0; q < 4; q++) {
            int idx = q * 128 + tid;
            int row = idx >> 3, c4 = idx & 7;
            As[(c4 * 4 + 0) * AS_STRIDE + row] = rA[q].x;
            As[(c4 * 4 + 1) * AS_STRIDE + row] = rA[q].y;
            As[(c4 * 4 + 2) * AS_STRIDE + row] = rA[q].z;
            As[(c4 * 4 + 3) * AS_STRIDE + row] = rA[q].w;
        }
        #pragma unroll
        for (int q = 0; q < 8; q++) {
            int idx = q * 128 + tid;
            int row = idx >> 5, c4 = idx & 31;
            *(float4*)&Bs[row * 128 + c4 * 4] = rB[q];
        }
    }
    __syncthreads();

    unsigned long long acc2[4][8];
    #pragma unroll
    for (int ip = 0; ip < 4; ip++)
        #pragma unroll
        for (int j = 0; j < 8; j++) acc2[ip][j] = 0ull;

    #pragma unroll
    for (int c = 0; c < 4; c++) {
        if (c < 3) {
            int k0 = (c + 1) * GEMM_BK;
            #pragma unroll
            for (int q = 0; q < 4; q++) {
                int idx = q * 128 + tid;
                int row = idx >> 3, c4 = idx & 7;
                int gr = rowBlock + row;
                rA[q] = (gr < N) ? *(const float4*)&A[(size_t)gr * FDIM + k0 + c4 * 4]
                                 : make_float4(0.f, 0.f, 0.f, 0.f);
            }
            #pragma unroll
            for (int q = 0; q < 8; q++) {
                int idx = q * 128 + tid;
                int row = idx >> 5, c4 = idx & 31;
                rB[q] = *(const float4*)&B[(size_t)(k0 + row) * FDIM + c4 * 4];
            }
        }

        const float* As = smem + (c & 1) * GEMM_STAGE_FLOATS;
        const float* Bs = As + GEMM_BK * AS_STRIDE;
        #pragma unroll 8
        for (int kk = 0; kk < GEMM_BK; kk++) {
            unsigned long long a2[4];
            float bf[8];
            *(float4*)&a2[0] = *(const float4*)&As[kk * AS_STRIDE + ty * 8];
            *(float4*)&a2[2] = *(const float4*)&As[kk * AS_STRIDE + ty * 8 + 4];
            *(float4*)&bf[0] = *(const float4*)&Bs[kk * 128 + tx * 8];
            *(float4*)&bf[4] = *(const float4*)&Bs[kk * 128 + tx * 8 + 4];
            #pragma unroll
            for (int j = 0; j < 8; j++) {
                unsigned long long bd = dup2(bf[j]);
                #pragma unroll
                for (int ip = 0; ip < 4; ip++)
                    ffma2(acc2[ip][j], a2[ip], bd);
            }
        }

        if (c < 3) {
            float* Asw = smem + ((c + 1) & 1) * GEMM_STAGE_FLOATS;
            float* Bsw = Asw + GEMM_BK * AS_STRIDE;
            #pragma unroll
            for (int q = 0; q < 4; q++) {
                int idx = q * 128 + tid;
                int row = idx >> 3, c4 = idx & 7;
                Asw[(c4 * 4 + 0) * AS_STRIDE + row] = rA[q].x;
                Asw[(c4 * 4 + 1) * AS_STRIDE + row] = rA[q].y;
                Asw[(c4 * 4 + 2) * AS_STRIDE + row] = rA[q].z;
                Asw[(c4 * 4 + 3) * AS_STRIDE + row] = rA[q].w;
            }
            #pragma unroll
            for (int q = 0; q < 8; q++) {
                int idx = q * 128 + tid;
                int row = idx >> 5, c4 = idx & 31;
                *(float4*)&Bsw[row * 128 + c4 * 4] = rB[q];
            }
        }
        __syncthreads();
    }

    float sa[8], da[8];
    #pragma unroll
    for (int j = 0; j < 8; j++) {
        sa[j] = att_s[tx * 8 + j];
        da[j] = att_d[tx * 8 + j];
    }
    int head = tx >> 2;
    #pragma unroll
    for (int i = 0; i < 8; i++) {
        int ip = i >> 1;
        float r[8];
        #pragma unroll
        for (int j = 0; j < 8; j++) {
            float2 p = *(float2*)&acc2[ip][j];
            r[j] = (i & 1) ? p.y : p.x;
        }
        int gr = rowBlock + ty * 8 + i;
        if (gr < N) {
            *(float4*)&C[(size_t)gr * FDIM + tx * 8]     = *(float4*)&r[0];
            *(float4*)&C[(size_t)gr * FDIM + tx * 8 + 4] = *(float4*)&r[4];
        }
        float ps = 0.f, pd = 0.f;
        #pragma unroll
        for (int j = 0; j < 8; j++) {
            ps += r[j] * sa[j];
            pd += r[j] * da[j];
        }
        ps += __shfl_down_sync(0xffffffffu, ps, 2);
        pd += __shfl_down_sync(0xffffffffu, pd, 2);
        ps += __shfl_down_sync(0xffffffffu, ps, 1);
        pd += __shfl_down_sync(0xffffffffu, pd, 1);
        if ((tx & 3) == 0 && gr < N) {
            as_[gr * HEADS + head] = ps;
            ad_[gr * HEADS + head] = pd;
        }
    }
}

// =============== fused softmax + aggregation ===============
__global__ void aggr_kernel(const int* __restrict__ csrc,
                            const int* __restrict__ rptr,
                            const int* __restrict__ cnt,
                            const float* __restrict__ as_,
                            const float* __restrict__ ad_,
                            const float* __restrict__ h,
                            const float* __restrict__ bias,
                            float* __restrict__ out, int N) {
    int gtid = blockIdx.x * blockDim.x + threadIdx.x;
    int dst = gtid >> 5;
    int lane = gtid & 31;
    if (dst >= N) return;
    int beg = rptr[dst];
    int deg = cnt[dst];
    int hd = lane >> 3;
    float adv = ad_[dst * HEADS + hd];
    float acc0 = 0.f, acc1 = 0.f, acc2 = 0.f, acc3 = 0.f;
    float ssum = 0.f;

    for (int i0 = 0; i0 < deg; i0 += 32) {
        int li = i0 + lane;
        int mySrc = csrc[beg + ((li < deg) ? li : (deg - 1))];
        int m = min(32, deg - i0);
        int j = 0;
        for (; j + 8 <= m; j += 8) {
            int s[8]; float asv[8]; float4 hv[8];
            #pragma unroll
            for (int q = 0; q < 8; q++)
                s[q] = __shfl_sync(0xffffffffu, mySrc, j + q);
            #pragma unroll
            for (int q = 0; q < 8; q++)
                asv[q] = as_[s[q] * HEADS + hd];
            #pragma unroll
            for (int q = 0; q < 8; q++)
                hv[q] = *(const float4*)&h[(size_t)s[q] * FDIM + lane * 4];
            #pragma unroll
            for (int q = 0; q < 8; q++) {
                float e = asv[q] + adv;
                e = (e > 0.f) ? e : 0.2f * e;
                float ex = __expf(e);
                ssum += ex;
                acc0 += hv[q].x * ex;
                acc1 += hv[q].y * ex;
                acc2 += hv[q].z * ex;
                acc3 += hv[q].w * ex;
            }
        }
        for (; j < m; j++) {
            int src = __shfl_sync(0xffffffffu, mySrc, j);
            float e = as_[src * HEADS + hd] + adv;
            e = (e > 0.f) ? e : 0.2f * e;
            float ex = __expf(e);
            ssum += ex;
            float4 hv = *(const float4*)&h[(size_t)src * FDIM + lane * 4];
            acc0 += hv.x * ex;
            acc1 += hv.y * ex;
            acc2 += hv.z * ex;
            acc3 += hv.w * ex;
        }
    }
    float inv = 1.f / (ssum + 1e-16f);
    float4 b4 = *(const float4*)&bias[lane * 4];
    float4 o = make_float4(acc0 * inv + b4.x, acc1 * inv + b4.y,
                           acc2 * inv + b4.z, acc3 * inv + b4.w);
    *(float4*)&out[(size_t)dst * FDIM + lane * 4] = o;
}

// =============== MLP head ===============
__global__ void mlp_kernel(const float* __restrict__ x3,
                           const float* __restrict__ x0,
                           const float* __restrict__ W1,
                           const float* __restrict__ b1,
                           const float* __restrict__ W2,
                           const float* __restrict__ b2,
                           float* __restrict__ out, int N) {
    __shared__ float W1s[256 * 32];
    __shared__ float W2s[32];
    __shared__ float b1s[32];
    int tid = threadIdx.x;
    for (int i = tid; i < 256 * 32; i += blockDim.x) W1s[i] = W1[i];
    if (tid < 32) { W2s[tid] = W2[tid]; b1s[tid] = b1[tid]; }
    __syncthreads();
    int warp = tid >> 5, lane = tid & 31;
    int node = blockIdx.x * (blockDim.x >> 5) + warp;
    if (node >= N) return;
    float acc = 0.f;
    #pragma unroll
    for (int blk = 0; blk < 8; blk++) {
        const float* xp = (blk < 4) ? &x3[(size_t)node * FDIM + blk * 32]
                                    : &x0[(size_t)node * FDIM + (blk - 4) * 32];
        float xv = xp[lane];
        #pragma unroll
        for (int i = 0; i < 32; i++) {
            float v = __shfl_sync(0xffffffffu, xv, i);
            acc += v * W1s[(blk * 32 + i) * 32 + lane];
        }
    }
    float hv = fmaxf(acc + b1s[lane], 0.f);
    float p = hv * W2s[lane];
    #pragma unroll
    for (int off = 16; off; off >>= 1)
        p += __shfl_down_sync(0xffffffffu, p, off);
    if (lane == 0)
        out[node] = 1.f / (1.f + __expf(-(p + b2[0])));
}

// =============== host launcher ===============
extern "C" void kernel_launch(void* const* d_in, const int* in_sizes, int n_in,
                              void* d_out, int out_size) {
    const float* x       = (const float*)d_in[0];
    const int*   ei      = (const int*)  d_in[1];
    const float* W       = (const float*)d_in[2];
    const float* att_src = (const float*)d_in[3];
    const float* att_dst = (const float*)d_in[4];
    const float* b_conv  = (const float*)d_in[5];
    const float* W1      = (const float*)d_in[6];
    const float* b1      = (const float*)d_in[7];
    const float* W2      = (const float*)d_in[8];
    const float* b2      = (const float*)d_in[9];

    int N  = in_sizes[0] / FDIM;
    int E  = in_sizes[1] / 2;
    int L  = in_sizes[2] / (FDIM * FDIM);
    int EP = E + N;

    float *hb, *xa, *xb, *asb, *adb;
    int *cnt, *rptr, *fill, *bsum, *csrc;
    cudaGetSymbolAddress((void**)&hb,   g_h);
    cudaGetSymbolAddress((void**)&xa,   g_xa);
    cudaGetSymbolAddress((void**)&xb,   g_xb);
    cudaGetSymbolAddress((void**)&asb,  g_as);
    cudaGetSymbolAddress((void**)&adb,  g_ad);
    cudaGetSymbolAddress((void**)&cnt,  g_cnt);
    cudaGetSymbolAddress((void**)&rptr, g_rptr);
    cudaGetSymbolAddress((void**)&fill, g_fill);
    cudaGetSymbolAddress((void**)&bsum, g_bsum);
    cudaGetSymbolAddress((void**)&csrc, g_csrc);

    static bool init_done = false;
    static cudaStream_t s2;
    static cudaEvent_t ev0, ev1;
    if (!init_done) {
        cudaFuncSetAttribute(gemm_kernel,
                             cudaFuncAttributeMaxDynamicSharedMemorySize,
                             GEMM_SMEM_BYTES);
        cudaStreamCreateWithFlags(&s2, cudaStreamNonBlocking);
        cudaEventCreateWithFlags(&ev0, cudaEventDisableTiming);
        cudaEventCreateWithFlags(&ev1, cudaEventDisableTiming);
        init_done = true;
    }

    int nb_scan = (N + 1023) / 1024;
    int gemm_grid = (N + GEMM_BM - 1) / GEMM_BM;
    int aggr_grid = (int)(((size_t)N * 32 + 255) / 256);
    float* bufs[2] = {xa, xb};

    // ---- fork: fast CSR chain on s2, concurrent with gemm0 on main ----
    cudaEventRecord(ev0, 0);
    cudaStreamWaitEvent(s2, ev0, 0);
    cudaMemsetAsync(cnt, 0, (size_t)N * sizeof(int), s2);
    hist_kernel<<<(EP + 255) / 256, 256, 0, s2>>>(ei, cnt, E, EP);
    scan1_kernel<<<nb_scan, 256, 0, s2>>>(cnt, rptr, bsum, N);
    scan2_kernel<<<nb_scan, 256, 0, s2>>>(rptr, fill, bsum, N, nb_scan);
    scatter_kernel<<<(EP + 255) / 256, 256, 0, s2>>>(ei, fill, csrc, E, EP);
    cudaEventRecord(ev1, s2);

    // gemm0 overlaps the CSR build
    gemm_kernel<<<gemm_grid, 128, GEMM_SMEM_BYTES>>>(
        x, W, att_src, att_dst, hb, asb, adb, N);
    cudaStreamWaitEvent(0, ev1, 0);   // join before aggr0

    const float* xin;
    for (int l = 0; l < L; l++) {
        float* outb = bufs[l & 1];
        if (l > 0) {
            gemm_kernel<<<gemm_grid, 128, GEMM_SMEM_BYTES>>>(
                bufs[(l - 1) & 1], W + (size_t)l * FDIM * FDIM,
                att_src + l * HEADS * CH, att_dst + l * HEADS * CH,
                hb, asb, adb, N);
        }
        aggr_kernel<<<aggr_grid, 256>>>(csrc, rptr, cnt, asb, adb, hb,
                                        b_conv + l * FDIM, outb, N);
        xin = outb;
    }
    mlp_kernel<<<(N + 7) / 8, 256>>>(xin, x, W1, b1, W2, b2, (float*)d_out, N);
}